// round 1
// baseline (speedup 1.0000x reference)
#include <cuda_runtime.h>
#include <math.h>

#define BB 4
#define SS 2048
#define DIMX 1024
#define DQK 128
#define DV 1024

// ---------------- scratch (device globals; no dynamic allocation) ----------------
__device__ float g_q[BB * SS * DQK];
__device__ float g_k[BB * SS * DQK];
__device__ float g_v[BB * SS * DV];
__device__ float g_attn[(size_t)BB * SS * SS];
__device__ float g_bias[SS];

// ---------------- small helpers ----------------
__device__ __forceinline__ float silu_f(float x) {
    return x / (1.0f + expf(-x));
}
__device__ __forceinline__ float lapl_f(float x) {
    // 0.5*(1+erf((x-mu)/(std*sqrt(2)))), mu=sqrt(0.5), std=sqrt(0.25*pi)
    return 0.5f * (1.0f + erff((x - 0.70710678118654746f) * 0.79788456080286541f));
}

// ---------------- rel-pos bias table: bias_d = table[bucket(d)] * sqrt(128) ------
__global__ void bias_kernel(const float* __restrict__ table) {
    int d = blockIdx.x * blockDim.x + threadIdx.x;
    if (d >= SS) return;
    int bkt;
    if (d < 16) {
        bkt = d;
    } else {
        float t = logf((float)d * 0.0625f) * (16.0f / 2.0794415416798357f);
        int v = 16 + (int)t;
        bkt = v < 31 ? v : 31;
    }
    g_bias[d] = table[bkt] * 11.313708498984761f;  // sqrt(128)
}

// ================= SGEMM tile config: 128x128x8, 256 thr, 8x8 micro (4+4 split) ==

// ---------------- kernel 1: q,k projections ----------------
__global__ __launch_bounds__(256, 2) void proj_qk_kernel(
    const float* __restrict__ x, const float* __restrict__ wqk,
    const float* __restrict__ bqk, const float* __restrict__ gamma,
    const float* __restrict__ beta)
{
    __shared__ __align__(16) float As[8][132];
    __shared__ __align__(16) float Bs[8][132];
    const int tid = threadIdx.x;
    const int mt = blockIdx.x;
    const float* A = x + (size_t)mt * 128 * DIMX;
    const int tx = tid & 15, ty = tid >> 4;
    const int arow = tid >> 1, ak = (tid & 1) * 4;
    const int bk = tid >> 5, bcol = (tid & 31) * 4;

    float acc[8][8];
#pragma unroll
    for (int i = 0; i < 8; i++)
#pragma unroll
        for (int j = 0; j < 8; j++) acc[i][j] = 0.0f;

    float4 av = *(const float4*)(A + (size_t)arow * DIMX + ak);
    float4 bv = *(const float4*)(wqk + (size_t)bk * DQK + bcol);

    for (int kc = 0; kc < DIMX; kc += 8) {
        As[ak + 0][arow] = av.x; As[ak + 1][arow] = av.y;
        As[ak + 2][arow] = av.z; As[ak + 3][arow] = av.w;
        *(float4*)&Bs[bk][bcol] = bv;
        __syncthreads();
        if (kc + 8 < DIMX) {
            av = *(const float4*)(A + (size_t)arow * DIMX + (kc + 8) + ak);
            bv = *(const float4*)(wqk + (size_t)(kc + 8 + bk) * DQK + bcol);
        }
#pragma unroll
        for (int kk = 0; kk < 8; kk++) {
            float a[8], b[8];
            *(float4*)(a)     = *(const float4*)&As[kk][ty * 4];
            *(float4*)(a + 4) = *(const float4*)&As[kk][ty * 4 + 64];
            *(float4*)(b)     = *(const float4*)&Bs[kk][tx * 4];
            *(float4*)(b + 4) = *(const float4*)&Bs[kk][tx * 4 + 64];
#pragma unroll
            for (int i = 0; i < 8; i++)
#pragma unroll
                for (int j = 0; j < 8; j++)
                    acc[i][j] = fmaf(a[i], b[j], acc[i][j]);
        }
        __syncthreads();
    }

    const int rowBase = mt * 128;
#pragma unroll
    for (int i = 0; i < 8; i++) {
        int r = rowBase + (i < 4 ? ty * 4 + i : 64 + ty * 4 + (i - 4));
#pragma unroll
        for (int j = 0; j < 8; j++) {
            int c = (j < 4 ? tx * 4 + j : 64 + tx * 4 + (j - 4));
            float s = silu_f(acc[i][j] + bqk[c]);
            size_t o = (size_t)r * DQK + c;
            g_q[o] = s * gamma[c] + beta[c];
            g_k[o] = s * gamma[DQK + c] + beta[DQK + c];
        }
    }
}

// ---------------- kernel 2: v projection ----------------
__global__ __launch_bounds__(256, 2) void proj_v_kernel(
    const float* __restrict__ x, const float* __restrict__ wv,
    const float* __restrict__ bv_bias)
{
    __shared__ __align__(16) float As[8][132];
    __shared__ __align__(16) float Bs[8][132];
    const int tid = threadIdx.x;
    const int nt = blockIdx.x;
    const int mt = blockIdx.y;
    const float* A = x + (size_t)mt * 128 * DIMX;
    const float* Bw = wv + nt * 128;
    const int tx = tid & 15, ty = tid >> 4;
    const int arow = tid >> 1, ak = (tid & 1) * 4;
    const int bk = tid >> 5, bcol = (tid & 31) * 4;

    float acc[8][8];
#pragma unroll
    for (int i = 0; i < 8; i++)
#pragma unroll
        for (int j = 0; j < 8; j++) acc[i][j] = 0.0f;

    float4 av = *(const float4*)(A + (size_t)arow * DIMX + ak);
    float4 bv = *(const float4*)(Bw + (size_t)bk * DV + bcol);

    for (int kc = 0; kc < DIMX; kc += 8) {
        As[ak + 0][arow] = av.x; As[ak + 1][arow] = av.y;
        As[ak + 2][arow] = av.z; As[ak + 3][arow] = av.w;
        *(float4*)&Bs[bk][bcol] = bv;
        __syncthreads();
        if (kc + 8 < DIMX) {
            av = *(const float4*)(A + (size_t)arow * DIMX + (kc + 8) + ak);
            bv = *(const float4*)(Bw + (size_t)(kc + 8 + bk) * DV + bcol);
        }
#pragma unroll
        for (int kk = 0; kk < 8; kk++) {
            float a[8], b[8];
            *(float4*)(a)     = *(const float4*)&As[kk][ty * 4];
            *(float4*)(a + 4) = *(const float4*)&As[kk][ty * 4 + 64];
            *(float4*)(b)     = *(const float4*)&Bs[kk][tx * 4];
            *(float4*)(b + 4) = *(const float4*)&Bs[kk][tx * 4 + 64];
#pragma unroll
            for (int i = 0; i < 8; i++)
#pragma unroll
                for (int j = 0; j < 8; j++)
                    acc[i][j] = fmaf(a[i], b[j], acc[i][j]);
        }
        __syncthreads();
    }

    const int rowBase = mt * 128;
    const int colBase = nt * 128;
#pragma unroll
    for (int i = 0; i < 8; i++) {
        int r = rowBase + (i < 4 ? ty * 4 + i : 64 + ty * 4 + (i - 4));
#pragma unroll
        for (int j = 0; j < 8; j++) {
            int c = colBase + (j < 4 ? tx * 4 + j : 64 + tx * 4 + (j - 4));
            g_v[(size_t)r * DV + c] = silu_f(acc[i][j] + bv_bias[c]);
        }
    }
}

// ---------------- kernel 3: sim = q@k^T (causal tiles only) + epilogue ----------
__global__ __launch_bounds__(256, 2) void sim_kernel()
{
    __shared__ __align__(16) float As[8][132];
    __shared__ __align__(16) float Bs[8][132];
    const int tid = threadIdx.x;
    int t = blockIdx.x;               // lower-triangular tile index 0..135
    const int b = blockIdx.y;
    int it = 0;
    while ((it + 1) * (it + 2) / 2 <= t) it++;
    const int jt = t - it * (it + 1) / 2;

    const float* Aq = g_q + ((size_t)b * SS + it * 128) * DQK;
    const float* Bk = g_k + ((size_t)b * SS + jt * 128) * DQK;
    const int tx = tid & 15, ty = tid >> 4;
    const int arow = tid >> 1, ak = (tid & 1) * 4;

    float acc[8][8];
#pragma unroll
    for (int i = 0; i < 8; i++)
#pragma unroll
        for (int j = 0; j < 8; j++) acc[i][j] = 0.0f;

    float4 av = *(const float4*)(Aq + (size_t)arow * DQK + ak);
    float4 bv = *(const float4*)(Bk + (size_t)arow * DQK + ak);

    for (int kc = 0; kc < DQK; kc += 8) {
        As[ak + 0][arow] = av.x; As[ak + 1][arow] = av.y;
        As[ak + 2][arow] = av.z; As[ak + 3][arow] = av.w;
        Bs[ak + 0][arow] = bv.x; Bs[ak + 1][arow] = bv.y;
        Bs[ak + 2][arow] = bv.z; Bs[ak + 3][arow] = bv.w;
        __syncthreads();
        if (kc + 8 < DQK) {
            av = *(const float4*)(Aq + (size_t)arow * DQK + (kc + 8) + ak);
            bv = *(const float4*)(Bk + (size_t)arow * DQK + (kc + 8) + ak);
        }
#pragma unroll
        for (int kk = 0; kk < 8; kk++) {
            float a[8], bb[8];
            *(float4*)(a)      = *(const float4*)&As[kk][ty * 4];
            *(float4*)(a + 4)  = *(const float4*)&As[kk][ty * 4 + 64];
            *(float4*)(bb)     = *(const float4*)&Bs[kk][tx * 4];
            *(float4*)(bb + 4) = *(const float4*)&Bs[kk][tx * 4 + 64];
#pragma unroll
            for (int i = 0; i < 8; i++)
#pragma unroll
                for (int j = 0; j < 8; j++)
                    acc[i][j] = fmaf(a[i], bb[j], acc[i][j]);
        }
        __syncthreads();
    }

    const float invS = 1.0f / (float)SS;
    float* out = g_attn + (size_t)b * SS * SS;
#pragma unroll
    for (int i = 0; i < 8; i++) {
        int gi = it * 128 + (i < 4 ? ty * 4 + i : 64 + ty * 4 + (i - 4));
#pragma unroll
        for (int j = 0; j < 8; j++) {
            int gj = jt * 128 + (j < 4 ? tx * 4 + j : 64 + tx * 4 + (j - 4));
            float val = 0.0f;
            if (gj <= gi) {
                float s = acc[i][j] * invS + g_bias[gi - gj];
                val = lapl_f(s);
            }
            out[(size_t)gi * SS + gj] = val;
        }
    }
}

// ---------------- kernel 4: out = attn @ v (causal K-extent) ----------------
__global__ __launch_bounds__(256, 2) void out_kernel(float* __restrict__ out)
{
    __shared__ __align__(16) float As[8][132];
    __shared__ __align__(16) float Bs[8][132];
    const int tid = threadIdx.x;
    const int nt = blockIdx.x;
    const int it = 15 - blockIdx.y;   // heaviest tiles launch first
    const int b = blockIdx.z;
    const int Kext = (it + 1) * 128;

    const float* A  = g_attn + ((size_t)b * SS + it * 128) * SS;
    const float* Bv = g_v + (size_t)b * SS * DV + nt * 128;
    const int tx = tid & 15, ty = tid >> 4;
    const int arow = tid >> 1, ak = (tid & 1) * 4;
    const int bk = tid >> 5, bcol = (tid & 31) * 4;

    float acc[8][8];
#pragma unroll
    for (int i = 0; i < 8; i++)
#pragma unroll
        for (int j = 0; j < 8; j++) acc[i][j] = 0.0f;

    float4 av = *(const float4*)(A + (size_t)arow * SS + ak);
    float4 bv = *(const float4*)(Bv + (size_t)bk * DV + bcol);

    for (int kc = 0; kc < Kext; kc += 8) {
        As[ak + 0][arow] = av.x; As[ak + 1][arow] = av.y;
        As[ak + 2][arow] = av.z; As[ak + 3][arow] = av.w;
        *(float4*)&Bs[bk][bcol] = bv;
        __syncthreads();
        if (kc + 8 < Kext) {
            av = *(const float4*)(A + (size_t)arow * SS + (kc + 8) + ak);
            bv = *(const float4*)(Bv + (size_t)(kc + 8 + bk) * DV + bcol);
        }
#pragma unroll
        for (int kk = 0; kk < 8; kk++) {
            float a[8], bb[8];
            *(float4*)(a)      = *(const float4*)&As[kk][ty * 4];
            *(float4*)(a + 4)  = *(const float4*)&As[kk][ty * 4 + 64];
            *(float4*)(bb)     = *(const float4*)&Bs[kk][tx * 4];
            *(float4*)(bb + 4) = *(const float4*)&Bs[kk][tx * 4 + 64];
#pragma unroll
            for (int i = 0; i < 8; i++)
#pragma unroll
                for (int j = 0; j < 8; j++)
                    acc[i][j] = fmaf(a[i], bb[j], acc[i][j]);
        }
        __syncthreads();
    }

    const int rowBase = it * 128;
    const int colBase = nt * 128;
#pragma unroll
    for (int i = 0; i < 8; i++) {
        int r = rowBase + (i < 4 ? ty * 4 + i : 64 + ty * 4 + (i - 4));
#pragma unroll
        for (int j = 0; j < 8; j++) {
            int c = colBase + (j < 4 ? tx * 4 + j : 64 + tx * 4 + (j - 4));
            out[((size_t)b * SS + r) * DV + c] = acc[i][j];
        }
    }
}

// ---------------- launch ----------------
extern "C" void kernel_launch(void* const* d_in, const int* in_sizes, int n_in,
                              void* d_out, int out_size)
{
    const float* x     = (const float*)d_in[0];
    const float* wqk   = (const float*)d_in[1];
    const float* bqk   = (const float*)d_in[2];
    const float* gamma = (const float*)d_in[3];
    const float* beta  = (const float*)d_in[4];
    const float* wv    = (const float*)d_in[5];
    const float* bv    = (const float*)d_in[6];
    const float* rel   = (const float*)d_in[7];
    float* out = (float*)d_out;

    bias_kernel<<<(SS + 255) / 256, 256>>>(rel);
    proj_qk_kernel<<<BB * SS / 128, 256>>>(x, wqk, bqk, gamma, beta);
    proj_v_kernel<<<dim3(DV / 128, BB * SS / 128), 256>>>(x, wv, bv);
    sim_kernel<<<dim3(136, BB), 256>>>();
    out_kernel<<<dim3(DV / 128, SS / 128, BB), 256>>>(out);
}

// round 4
// speedup vs baseline: 2.3128x; 2.3128x over previous
#include <cuda_runtime.h>
#include <cuda_bf16.h>
#include <math.h>
#include <stdint.h>

#define BB 4
#define SS 2048
#define DIMX 1024
#define DQK 128
#define DV 1024
#define MROWS (BB * SS)   // 8192

// ---------------------------------------------------------------------------
// scratch (__device__ globals; no dynamic allocation)
// ---------------------------------------------------------------------------
__device__ __align__(256) __nv_bfloat16 g_xhi[(size_t)MROWS * DIMX];
__device__ __align__(256) __nv_bfloat16 g_xlo[(size_t)MROWS * DIMX];
__device__ __align__(256) __nv_bfloat16 g_wqk_hi[DIMX * DQK];   // [k][n] natural
__device__ __align__(256) __nv_bfloat16 g_wqk_lo[DIMX * DQK];
__device__ __align__(256) __nv_bfloat16 g_wv_hi[(size_t)DIMX * DV];
__device__ __align__(256) __nv_bfloat16 g_wv_lo[(size_t)DIMX * DV];
__device__ __align__(256) __nv_bfloat16 g_qhi[(size_t)MROWS * DQK];
__device__ __align__(256) __nv_bfloat16 g_qlo[(size_t)MROWS * DQK];
__device__ __align__(256) __nv_bfloat16 g_khi[(size_t)MROWS * DQK];
__device__ __align__(256) __nv_bfloat16 g_klo[(size_t)MROWS * DQK];
__device__ __align__(256) __nv_bfloat16 g_vhi[(size_t)MROWS * DV];   // [row][dv] natural
__device__ __align__(256) __nv_bfloat16 g_vlo[(size_t)MROWS * DV];
__device__ __align__(256) __nv_bfloat16 g_ahi[(size_t)BB * SS * SS];
__device__ __align__(256) __nv_bfloat16 g_alo[(size_t)BB * SS * SS];
__device__ float g_bias[SS];

// ---------------------------------------------------------------------------
// helpers
// ---------------------------------------------------------------------------
__device__ __forceinline__ uint32_t smem_to_u32(const void* p) {
    uint32_t a;
    asm("{ .reg .u64 t; cvta.to.shared.u64 t, %1; cvt.u32.u64 %0, t; }"
        : "=r"(a) : "l"(p));
    return a;
}
__device__ __forceinline__ uint32_t sw128(uint32_t o) {
    return o ^ ((o >> 3) & 0x70);
}
__device__ __forceinline__ void cp16(uint32_t dst, const void* src) {
    asm volatile("cp.async.cg.shared.global [%0], [%1], 16;" :: "r"(dst), "l"(src));
}
__device__ __forceinline__ void ldmx4(uint32_t* r, uint32_t a) {
    asm volatile("ldmatrix.sync.aligned.m8n8.x4.shared.b16 {%0,%1,%2,%3}, [%4];"
        : "=r"(r[0]), "=r"(r[1]), "=r"(r[2]), "=r"(r[3]) : "r"(a));
}
__device__ __forceinline__ void ldmx4t(uint32_t* r, uint32_t a) {
    asm volatile("ldmatrix.sync.aligned.m8n8.x4.trans.shared.b16 {%0,%1,%2,%3}, [%4];"
        : "=r"(r[0]), "=r"(r[1]), "=r"(r[2]), "=r"(r[3]) : "r"(a));
}
__device__ __forceinline__ void mma16816(float* d, const uint32_t* a, const uint32_t* b) {
    asm volatile(
        "mma.sync.aligned.m16n8k16.row.col.f32.bf16.bf16.f32 "
        "{%0,%1,%2,%3}, {%4,%5,%6,%7}, {%8,%9}, {%0,%1,%2,%3};"
        : "+f"(d[0]), "+f"(d[1]), "+f"(d[2]), "+f"(d[3])
        : "r"(a[0]), "r"(a[1]), "r"(a[2]), "r"(a[3]), "r"(b[0]), "r"(b[1]));
}

__device__ __forceinline__ float silu_f(float x) { return x / (1.0f + expf(-x)); }
__device__ __forceinline__ float lapl_f(float x) {
    return 0.5f * (1.0f + erff((x - 0.70710678118654746f) * 0.79788456080286541f));
}
// split pair of floats -> packed bf16 hi pair / bf16 lo pair
__device__ __forceinline__ void split2(float a, float b, uint32_t& hi, uint32_t& lo) {
    __nv_bfloat16 ah = __float2bfloat16_rn(a), bh = __float2bfloat16_rn(b);
    float ar = a - __bfloat162float(ah), br = b - __bfloat162float(bh);
    __nv_bfloat162 h2 = __halves2bfloat162(ah, bh);
    __nv_bfloat162 l2 = __floats2bfloat162_rn(ar, br);
    hi = *reinterpret_cast<uint32_t*>(&h2);
    lo = *reinterpret_cast<uint32_t*>(&l2);
}

// ---------------------------------------------------------------------------
// tile geometry: CTA 128x128, chunk K=64, 256 threads, 8 warps (4m x 2n),
// warp tile 32x64. A/B(nmajor) tiles: 128 rows x 128B, SW128 swizzle.
// B(kmajor/trans) tiles: 64 rows x 272B (256B data + 16B pad).
// ---------------------------------------------------------------------------
#define TILE_NM 16384           // 128 * 128B
#define TILE_KM 17408           // 64 * 272B
#define OFF_ALO 16384
#define OFF_BHI 32768
#define OFF_BLO 50176
#define STAGE_B 67584           // 2*16384 + 2*17408
#define SMEM_DYN (2 * STAGE_B)  // 135168

__device__ __forceinline__ void ld_tile_nmajor(uint32_t dst, const __nv_bfloat16* src,
                                               int ld, int tid) {
#pragma unroll
    for (int s = 0; s < 4; s++) {
        int idx = tid + s * 256;
        int row = idx >> 3, seg = idx & 7;
        uint32_t off = (uint32_t)(row * 128 + seg * 16);
        cp16(dst + sw128(off), src + (size_t)row * ld + seg * 8);
    }
}
__device__ __forceinline__ void ld_tile_kmajor(uint32_t dst, const __nv_bfloat16* src,
                                               int ld, int tid) {
#pragma unroll
    for (int s = 0; s < 4; s++) {
        int idx = tid + s * 256;
        int row = idx >> 4, seg = idx & 15;
        cp16(dst + (uint32_t)(row * 272 + seg * 16), src + (size_t)row * ld + seg * 8);
    }
}

template <bool BTRANS>
__device__ __forceinline__ void compute_stage(uint32_t st, float acc[2][8][4], int tid) {
    const int lane = tid & 31, wid = tid >> 5, wm = wid & 3, wn = wid >> 2;
    // RAW (unswizzled) offsets; swizzle applied after adding the k-step delta.
    uint32_t a_raw[2];
#pragma unroll
    for (int i = 0; i < 2; i++) {
        uint32_t row = wm * 32 + i * 16 + (lane & 15);
        a_raw[i] = row * 128 + ((lane >> 4) << 4);
    }
    uint32_t b_raw[4];
    const uint32_t m = lane >> 3;
    if (!BTRANS) {
#pragma unroll
        for (int g = 0; g < 4; g++) {
            uint32_t row = wn * 64 + g * 16 + ((m >> 1) << 3) + (lane & 7);
            b_raw[g] = row * 128 + ((m & 1) << 4);
        }
    } else {
#pragma unroll
        for (int g = 0; g < 4; g++) {
            uint32_t krow = ((m & 1) << 3) + (lane & 7);
            uint32_t ncol = wn * 64 + g * 16 + ((m >> 1) << 3);
            b_raw[g] = krow * 272 + ncol * 2;
        }
    }
    const uint32_t Ahi_s = st, Alo_s = st + OFF_ALO;
    const uint32_t Bhi_s = st + OFF_BHI, Blo_s = st + OFF_BLO;
#pragma unroll
    for (int ks = 0; ks < 4; ks++) {
        uint32_t ah[2][4], al[2][4], bh[4][4], bl[4][4];
#pragma unroll
        for (int i = 0; i < 2; i++) {
            uint32_t ao = sw128(a_raw[i] + ks * 32);
            ldmx4(ah[i], Ahi_s + ao);
            ldmx4(al[i], Alo_s + ao);
        }
        if (!BTRANS) {
#pragma unroll
            for (int g = 0; g < 4; g++) {
                uint32_t bo = sw128(b_raw[g] + ks * 32);
                ldmx4(bh[g], Bhi_s + bo);
                ldmx4(bl[g], Blo_s + bo);
            }
        } else {
#pragma unroll
            for (int g = 0; g < 4; g++) {
                uint32_t bo = b_raw[g] + ks * 4352;   // unswizzled padded tile
                ldmx4t(bh[g], Bhi_s + bo);
                ldmx4t(bl[g], Blo_s + bo);
            }
        }
#pragma unroll
        for (int i = 0; i < 2; i++)
#pragma unroll
            for (int j = 0; j < 8; j++) {
                const uint32_t* bhj = &bh[j >> 1][(j & 1) * 2];
                const uint32_t* blj = &bl[j >> 1][(j & 1) * 2];
                mma16816(acc[i][j], ah[i], bhj);
                mma16816(acc[i][j], ah[i], blj);
                mma16816(acc[i][j], al[i], bhj);
            }
    }
}

template <bool BTRANS>
__device__ __forceinline__ void gemm_run(uint32_t sb, float acc[2][8][4],
    const __nv_bfloat16* Ahi, const __nv_bfloat16* Alo, int lda,
    const __nv_bfloat16* Bhi, const __nv_bfloat16* Blo, int ldb, int nk)
{
    const int tid = threadIdx.x;
#pragma unroll
    for (int i = 0; i < 2; i++)
#pragma unroll
        for (int j = 0; j < 8; j++)
#pragma unroll
            for (int r = 0; r < 4; r++) acc[i][j][r] = 0.0f;

#define LOAD_CHUNK(stg, c) do {                                                   \
        uint32_t base_ = sb + (stg) * STAGE_B;                                    \
        ld_tile_nmajor(base_, Ahi + (size_t)(c) * 64, lda, tid);                  \
        ld_tile_nmajor(base_ + OFF_ALO, Alo + (size_t)(c) * 64, lda, tid);        \
        if (BTRANS) {                                                             \
            ld_tile_kmajor(base_ + OFF_BHI, Bhi + (size_t)(c) * 64 * ldb, ldb, tid); \
            ld_tile_kmajor(base_ + OFF_BLO, Blo + (size_t)(c) * 64 * ldb, ldb, tid); \
        } else {                                                                  \
            ld_tile_nmajor(base_ + OFF_BHI, Bhi + (size_t)(c) * 64, ldb, tid);    \
            ld_tile_nmajor(base_ + OFF_BLO, Blo + (size_t)(c) * 64, ldb, tid);    \
        }                                                                         \
    } while (0)

    LOAD_CHUNK(0, 0);
    asm volatile("cp.async.commit_group;");
    for (int i = 0; i < nk; i++) {
        int st = i & 1;
        if (i + 1 < nk) {
            LOAD_CHUNK(st ^ 1, i + 1);
            asm volatile("cp.async.commit_group;");
            asm volatile("cp.async.wait_group 1;");
        } else {
            asm volatile("cp.async.wait_group 0;");
        }
        __syncthreads();
        compute_stage<BTRANS>(sb + st * STAGE_B, acc, tid);
        __syncthreads();
    }
#undef LOAD_CHUNK
}

// ---------------------------------------------------------------------------
// prep kernels
// ---------------------------------------------------------------------------
__global__ void bias_kernel(const float* __restrict__ table) {
    int d = blockIdx.x * blockDim.x + threadIdx.x;
    if (d >= SS) return;
    int bkt;
    if (d < 16) {
        bkt = d;
    } else {
        float t = logf((float)d * 0.0625f) * (16.0f / 2.0794415416798357f);
        int v = 16 + (int)t;
        bkt = v < 31 ? v : 31;
    }
    g_bias[d] = table[bkt] * 11.313708498984761f;
}
__global__ void split_f_kernel(const float* __restrict__ src, __nv_bfloat16* hi,
                               __nv_bfloat16* lo, size_t n) {
    size_t i = (size_t)blockIdx.x * blockDim.x + threadIdx.x;
    if (i >= n) return;
    float f = src[i];
    __nv_bfloat16 h = __float2bfloat16_rn(f);
    hi[i] = h;
    lo[i] = __float2bfloat16_rn(f - __bfloat162float(h));
}

// ---------------------------------------------------------------------------
// GEMM kernels
// ---------------------------------------------------------------------------
__global__ __launch_bounds__(256, 1) void tc_proj_qk(
    const float* __restrict__ bqk, const float* __restrict__ gamma,
    const float* __restrict__ beta)
{
    extern __shared__ __align__(1024) char smem[];
    uint32_t sb = smem_to_u32(smem);
    const int mt = blockIdx.x;
    float acc[2][8][4];
    gemm_run<true>(sb, acc,
                   g_xhi + (size_t)mt * 128 * DIMX, g_xlo + (size_t)mt * 128 * DIMX, DIMX,
                   g_wqk_hi, g_wqk_lo, DQK, DIMX / 64);
    const int tid = threadIdx.x, lane = tid & 31, wid = tid >> 5;
    const int wm = wid & 3, wn = wid >> 2, t4 = lane >> 2, tm4 = lane & 3;
#pragma unroll
    for (int i = 0; i < 2; i++)
#pragma unroll
        for (int rr = 0; rr < 2; rr++) {
            int row = mt * 128 + wm * 32 + i * 16 + t4 + 8 * rr;
#pragma unroll
            for (int j = 0; j < 8; j++) {
                int c = wn * 64 + j * 8 + 2 * tm4;
                float f0 = silu_f(acc[i][j][2 * rr + 0] + bqk[c]);
                float f1 = silu_f(acc[i][j][2 * rr + 1] + bqk[c + 1]);
                float q0 = f0 * gamma[c] + beta[c];
                float q1 = f1 * gamma[c + 1] + beta[c + 1];
                float k0 = f0 * gamma[DQK + c] + beta[DQK + c];
                float k1 = f1 * gamma[DQK + c + 1] + beta[DQK + c + 1];
                uint32_t qh, ql, kh, kl;
                split2(q0, q1, qh, ql);
                split2(k0, k1, kh, kl);
                size_t o = (size_t)row * DQK + c;
                *reinterpret_cast<uint32_t*>(g_qhi + o) = qh;
                *reinterpret_cast<uint32_t*>(g_qlo + o) = ql;
                *reinterpret_cast<uint32_t*>(g_khi + o) = kh;
                *reinterpret_cast<uint32_t*>(g_klo + o) = kl;
            }
        }
}

__global__ __launch_bounds__(256, 1) void tc_proj_v(const float* __restrict__ bv)
{
    extern __shared__ __align__(1024) char smem[];
    uint32_t sb = smem_to_u32(smem);
    const int nt = blockIdx.x, mt = blockIdx.y;
    float acc[2][8][4];
    gemm_run<true>(sb, acc,
                   g_xhi + (size_t)mt * 128 * DIMX, g_xlo + (size_t)mt * 128 * DIMX, DIMX,
                   g_wv_hi + nt * 128, g_wv_lo + nt * 128, DV, DIMX / 64);
    const int tid = threadIdx.x, lane = tid & 31, wid = tid >> 5;
    const int wm = wid & 3, wn = wid >> 2, t4 = lane >> 2, tm4 = lane & 3;
#pragma unroll
    for (int i = 0; i < 2; i++)
#pragma unroll
        for (int rr = 0; rr < 2; rr++) {
            int row = mt * 128 + wm * 32 + i * 16 + t4 + 8 * rr;
#pragma unroll
            for (int j = 0; j < 8; j++) {
                int c = nt * 128 + wn * 64 + j * 8 + 2 * tm4;
                float f0 = silu_f(acc[i][j][2 * rr + 0] + bv[c]);
                float f1 = silu_f(acc[i][j][2 * rr + 1] + bv[c + 1]);
                uint32_t vh, vl;
                split2(f0, f1, vh, vl);
                size_t o = (size_t)row * DV + c;
                *reinterpret_cast<uint32_t*>(g_vhi + o) = vh;
                *reinterpret_cast<uint32_t*>(g_vlo + o) = vl;
            }
        }
}

__global__ __launch_bounds__(256, 1) void tc_sim()
{
    extern __shared__ __align__(1024) char smem[];
    uint32_t sb = smem_to_u32(smem);
    int t = blockIdx.x;
    const int b = blockIdx.y;
    int it = 0;
    while ((it + 1) * (it + 2) / 2 <= t) it++;
    const int jt = t - it * (it + 1) / 2;
    const size_t qoff = ((size_t)b * SS + it * 128) * DQK;
    const size_t koff = ((size_t)b * SS + jt * 128) * DQK;
    float acc[2][8][4];
    gemm_run<false>(sb, acc, g_qhi + qoff, g_qlo + qoff, DQK,
                    g_khi + koff, g_klo + koff, DQK, DQK / 64);
    const int tid = threadIdx.x, lane = tid & 31, wid = tid >> 5;
    const int wm = wid & 3, wn = wid >> 2, t4 = lane >> 2, tm4 = lane & 3;
    const float invS = 1.0f / (float)SS;
    const size_t bb = (size_t)b * SS * SS;
#pragma unroll
    for (int i = 0; i < 2; i++)
#pragma unroll
        for (int rr = 0; rr < 2; rr++) {
            int gi = it * 128 + wm * 32 + i * 16 + t4 + 8 * rr;
#pragma unroll
            for (int j = 0; j < 8; j++) {
                int gj = jt * 128 + wn * 64 + j * 8 + 2 * tm4;
                float v0 = 0.0f, v1 = 0.0f;
                if (gj <= gi)
                    v0 = lapl_f(acc[i][j][2 * rr + 0] * invS + g_bias[gi - gj]);
                if (gj + 1 <= gi)
                    v1 = lapl_f(acc[i][j][2 * rr + 1] * invS + g_bias[gi - gj - 1]);
                uint32_t ah, al;
                split2(v0, v1, ah, al);
                size_t o = bb + (size_t)gi * SS + gj;
                *reinterpret_cast<uint32_t*>(g_ahi + o) = ah;
                *reinterpret_cast<uint32_t*>(g_alo + o) = al;
            }
        }
}

__global__ __launch_bounds__(256, 1) void tc_out(float* __restrict__ out)
{
    extern __shared__ __align__(1024) char smem[];
    uint32_t sb = smem_to_u32(smem);
    const int nt = blockIdx.x;
    const int it = 15 - blockIdx.y;   // heaviest first
    const int b = blockIdx.z;
    const int nk = (it + 1) * 2;
    const size_t aoff = ((size_t)b * SS + it * 128) * SS;
    float acc[2][8][4];
    gemm_run<true>(sb, acc, g_ahi + aoff, g_alo + aoff, SS,
                   g_vhi + (size_t)b * SS * DV + nt * 128,
                   g_vlo + (size_t)b * SS * DV + nt * 128, DV, nk);
    const int tid = threadIdx.x, lane = tid & 31, wid = tid >> 5;
    const int wm = wid & 3, wn = wid >> 2, t4 = lane >> 2, tm4 = lane & 3;
#pragma unroll
    for (int i = 0; i < 2; i++)
#pragma unroll
        for (int rr = 0; rr < 2; rr++) {
            int row = it * 128 + wm * 32 + i * 16 + t4 + 8 * rr;
#pragma unroll
            for (int j = 0; j < 8; j++) {
                int c = nt * 128 + wn * 64 + j * 8 + 2 * tm4;
                float2 v;
                v.x = acc[i][j][2 * rr + 0];
                v.y = acc[i][j][2 * rr + 1];
                *reinterpret_cast<float2*>(out + ((size_t)b * SS + row) * DV + c) = v;
            }
        }
}

// ---------------------------------------------------------------------------
// launch
// ---------------------------------------------------------------------------
extern "C" void kernel_launch(void* const* d_in, const int* in_sizes, int n_in,
                              void* d_out, int out_size)
{
    const float* x     = (const float*)d_in[0];
    const float* wqk   = (const float*)d_in[1];
    const float* bqk   = (const float*)d_in[2];
    const float* gamma = (const float*)d_in[3];
    const float* beta  = (const float*)d_in[4];
    const float* wv    = (const float*)d_in[5];
    const float* bv    = (const float*)d_in[6];
    const float* rel   = (const float*)d_in[7];
    float* out = (float*)d_out;

    cudaFuncSetAttribute(tc_proj_qk, cudaFuncAttributeMaxDynamicSharedMemorySize, SMEM_DYN);
    cudaFuncSetAttribute(tc_proj_v,  cudaFuncAttributeMaxDynamicSharedMemorySize, SMEM_DYN);
    cudaFuncSetAttribute(tc_sim,     cudaFuncAttributeMaxDynamicSharedMemorySize, SMEM_DYN);
    cudaFuncSetAttribute(tc_out,     cudaFuncAttributeMaxDynamicSharedMemorySize, SMEM_DYN);

    bias_kernel<<<(SS + 255) / 256, 256>>>(rel);
    {
        __nv_bfloat16 *xh, *xl, *wqh, *wql, *wvh, *wvl;
        cudaGetSymbolAddress((void**)&xh, g_xhi);
        cudaGetSymbolAddress((void**)&xl, g_xlo);
        cudaGetSymbolAddress((void**)&wqh, g_wqk_hi);
        cudaGetSymbolAddress((void**)&wql, g_wqk_lo);
        cudaGetSymbolAddress((void**)&wvh, g_wv_hi);
        cudaGetSymbolAddress((void**)&wvl, g_wv_lo);
        size_t nx = (size_t)MROWS * DIMX;
        split_f_kernel<<<(unsigned)((nx + 255) / 256), 256>>>(x, xh, xl, nx);
        split_f_kernel<<<(DIMX * DQK + 255) / 256, 256>>>(wqk, wqh, wql, DIMX * DQK);
        size_t nw = (size_t)DIMX * DV;
        split_f_kernel<<<(unsigned)((nw + 255) / 256), 256>>>(wv, wvh, wvl, nw);
    }

    tc_proj_qk<<<MROWS / 128, 256, SMEM_DYN>>>(bqk, gamma, beta);
    tc_proj_v<<<dim3(DV / 128, MROWS / 128), 256, SMEM_DYN>>>(bv);
    tc_sim<<<dim3(136, BB), 256, SMEM_DYN>>>();
    tc_out<<<dim3(DV / 128, SS / 128, BB), 256, SMEM_DYN>>>(out);
}

// round 5
// speedup vs baseline: 2.6347x; 1.1392x over previous
#include <cuda_runtime.h>
#include <cuda_bf16.h>
#include <cuda_fp16.h>
#include <math.h>
#include <stdint.h>

#define BB 4
#define SS 2048
#define DIMX 1024
#define DQK 128
#define DV 1024
#define MROWS (BB * SS)   // 8192

// ---------------------------------------------------------------------------
// scratch (__device__ globals; no dynamic allocation)
// ---------------------------------------------------------------------------
__device__ __align__(256) __nv_bfloat16 g_xhi[(size_t)MROWS * DIMX];
__device__ __align__(256) __nv_bfloat16 g_xlo[(size_t)MROWS * DIMX];
__device__ __align__(256) __nv_bfloat16 g_wqk_hi[DIMX * DQK];   // [k][n] natural
__device__ __align__(256) __nv_bfloat16 g_wqk_lo[DIMX * DQK];
__device__ __align__(256) __nv_bfloat16 g_wv_hi[(size_t)DIMX * DV];
__device__ __align__(256) __nv_bfloat16 g_wv_lo[(size_t)DIMX * DV];
__device__ __align__(256) __half g_q[(size_t)MROWS * DQK];           // fp16 single
__device__ __align__(256) __half g_k[(size_t)MROWS * DQK];           // fp16 single
__device__ __align__(256) __half g_vhi[(size_t)MROWS * DV];          // fp16 hi
__device__ __align__(256) __half g_vlo[(size_t)MROWS * DV];          // fp16 lo
__device__ __align__(256) __half g_attn[(size_t)BB * SS * SS];       // fp16 single
__device__ float g_bias[SS];

// ---------------------------------------------------------------------------
// helpers
// ---------------------------------------------------------------------------
__device__ __forceinline__ uint32_t smem_to_u32(const void* p) {
    uint32_t a;
    asm("{ .reg .u64 t; cvta.to.shared.u64 t, %1; cvt.u32.u64 %0, t; }"
        : "=r"(a) : "l"(p));
    return a;
}
__device__ __forceinline__ uint32_t sw128(uint32_t o) {
    return o ^ ((o >> 3) & 0x70);
}
__device__ __forceinline__ void cp16(uint32_t dst, const void* src) {
    asm volatile("cp.async.cg.shared.global [%0], [%1], 16;" :: "r"(dst), "l"(src));
}
__device__ __forceinline__ void ldmx4(uint32_t* r, uint32_t a) {
    asm volatile("ldmatrix.sync.aligned.m8n8.x4.shared.b16 {%0,%1,%2,%3}, [%4];"
        : "=r"(r[0]), "=r"(r[1]), "=r"(r[2]), "=r"(r[3]) : "r"(a));
}
__device__ __forceinline__ void ldmx4t(uint32_t* r, uint32_t a) {
    asm volatile("ldmatrix.sync.aligned.m8n8.x4.trans.shared.b16 {%0,%1,%2,%3}, [%4];"
        : "=r"(r[0]), "=r"(r[1]), "=r"(r[2]), "=r"(r[3]) : "r"(a));
}
template <bool F16>
__device__ __forceinline__ void mma16816(float* d, const uint32_t* a, const uint32_t* b) {
    if (F16) {
        asm volatile(
            "mma.sync.aligned.m16n8k16.row.col.f32.f16.f16.f32 "
            "{%0,%1,%2,%3}, {%4,%5,%6,%7}, {%8,%9}, {%0,%1,%2,%3};"
            : "+f"(d[0]), "+f"(d[1]), "+f"(d[2]), "+f"(d[3])
            : "r"(a[0]), "r"(a[1]), "r"(a[2]), "r"(a[3]), "r"(b[0]), "r"(b[1]));
    } else {
        asm volatile(
            "mma.sync.aligned.m16n8k16.row.col.f32.bf16.bf16.f32 "
            "{%0,%1,%2,%3}, {%4,%5,%6,%7}, {%8,%9}, {%0,%1,%2,%3};"
            : "+f"(d[0]), "+f"(d[1]), "+f"(d[2]), "+f"(d[3])
            : "r"(a[0]), "r"(a[1]), "r"(a[2]), "r"(a[3]), "r"(b[0]), "r"(b[1]));
    }
}

__device__ __forceinline__ float silu_f(float x) { return x / (1.0f + expf(-x)); }
__device__ __forceinline__ float lapl_f(float x) {
    return 0.5f * (1.0f + erff((x - 0.70710678118654746f) * 0.79788456080286541f));
}
// split pair of floats -> packed bf16 hi pair / bf16 lo pair
__device__ __forceinline__ void split2(float a, float b, uint32_t& hi, uint32_t& lo) {
    __nv_bfloat16 ah = __float2bfloat16_rn(a), bh = __float2bfloat16_rn(b);
    float ar = a - __bfloat162float(ah), br = b - __bfloat162float(bh);
    __nv_bfloat162 h2 = __halves2bfloat162(ah, bh);
    __nv_bfloat162 l2 = __floats2bfloat162_rn(ar, br);
    hi = *reinterpret_cast<uint32_t*>(&h2);
    lo = *reinterpret_cast<uint32_t*>(&l2);
}
// split pair of floats -> packed fp16 hi pair / fp16 lo pair
__device__ __forceinline__ void split2h(float a, float b, uint32_t& hi, uint32_t& lo) {
    __half ah = __float2half_rn(a), bh = __float2half_rn(b);
    float ar = a - __half2float(ah), br = b - __half2float(bh);
    __half2 h2 = __halves2half2(ah, bh);
    __half2 l2 = __floats2half2_rn(ar, br);
    hi = *reinterpret_cast<uint32_t*>(&h2);
    lo = *reinterpret_cast<uint32_t*>(&l2);
}
__device__ __forceinline__ uint32_t pack_h2(float a, float b) {
    __half2 h2 = __floats2half2_rn(a, b);
    return *reinterpret_cast<uint32_t*>(&h2);
}

// ---------------------------------------------------------------------------
// tile geometry: CTA 128x128, chunk K=64, 256 threads, 8 warps (4m x 2n),
// warp tile 32x64. A/B(nmajor) tiles: 128 rows x 128B, SW128 swizzle.
// B(kmajor/trans) tiles: 64 rows x 272B (256B data + 16B pad).
// ---------------------------------------------------------------------------
template <typename T>
__device__ __forceinline__ void ld_tile_nmajor(uint32_t dst, const T* src,
                                               int ld, int tid) {
#pragma unroll
    for (int s = 0; s < 4; s++) {
        int idx = tid + s * 256;
        int row = idx >> 3, seg = idx & 7;
        uint32_t off = (uint32_t)(row * 128 + seg * 16);
        cp16(dst + sw128(off), src + (size_t)row * ld + seg * 8);
    }
}
template <typename T>
__device__ __forceinline__ void ld_tile_kmajor(uint32_t dst, const T* src,
                                               int ld, int tid) {
#pragma unroll
    for (int s = 0; s < 4; s++) {
        int idx = tid + s * 256;
        int row = idx >> 4, seg = idx & 15;
        cp16(dst + (uint32_t)(row * 272 + seg * 16), src + (size_t)row * ld + seg * 8);
    }
}

template <bool BTRANS, bool ASPLIT, bool BSPLIT, bool F16>
__device__ __forceinline__ void compute_stage(uint32_t st, float acc[2][8][4], int tid) {
    constexpr int BTILE = BTRANS ? 17408 : 16384;
    constexpr uint32_t OFF_BH = ASPLIT ? 32768u : 16384u;
    constexpr uint32_t OFF_BL = OFF_BH + BTILE;
    const int lane = tid & 31, wid = tid >> 5, wm = wid & 3, wn = wid >> 2;
    uint32_t a_raw[2];
#pragma unroll
    for (int i = 0; i < 2; i++) {
        uint32_t row = wm * 32 + i * 16 + (lane & 15);
        a_raw[i] = row * 128 + ((lane >> 4) << 4);
    }
    uint32_t b_raw[4];
    const uint32_t m = lane >> 3;
    if (!BTRANS) {
#pragma unroll
        for (int g = 0; g < 4; g++) {
            uint32_t row = wn * 64 + g * 16 + ((m >> 1) << 3) + (lane & 7);
            b_raw[g] = row * 128 + ((m & 1) << 4);
        }
    } else {
#pragma unroll
        for (int g = 0; g < 4; g++) {
            uint32_t krow = ((m & 1) << 3) + (lane & 7);
            uint32_t ncol = wn * 64 + g * 16 + ((m >> 1) << 3);
            b_raw[g] = krow * 272 + ncol * 2;
        }
    }
    const uint32_t A_h = st, A_l = st + 16384;
    const uint32_t B_h = st + OFF_BH, B_l = st + OFF_BL;
#pragma unroll
    for (int ks = 0; ks < 4; ks++) {
        uint32_t ah[2][4], al[2][4], bh[4][4], bl[4][4];
#pragma unroll
        for (int i = 0; i < 2; i++) {
            uint32_t ao = sw128(a_raw[i] + ks * 32);
            ldmx4(ah[i], A_h + ao);
            if (ASPLIT) ldmx4(al[i], A_l + ao);
        }
        if (!BTRANS) {
#pragma unroll
            for (int g = 0; g < 4; g++) {
                uint32_t bo = sw128(b_raw[g] + ks * 32);
                ldmx4(bh[g], B_h + bo);
                if (BSPLIT) ldmx4(bl[g], B_l + bo);
            }
        } else {
#pragma unroll
            for (int g = 0; g < 4; g++) {
                uint32_t bo = b_raw[g] + ks * 4352;   // unswizzled padded tile
                ldmx4t(bh[g], B_h + bo);
                if (BSPLIT) ldmx4t(bl[g], B_l + bo);
            }
        }
#pragma unroll
        for (int i = 0; i < 2; i++)
#pragma unroll
            for (int j = 0; j < 8; j++) {
                const uint32_t* bhj = &bh[j >> 1][(j & 1) * 2];
                mma16816<F16>(acc[i][j], ah[i], bhj);
                if (BSPLIT) {
                    const uint32_t* blj = &bl[j >> 1][(j & 1) * 2];
                    mma16816<F16>(acc[i][j], ah[i], blj);
                }
                if (ASPLIT) mma16816<F16>(acc[i][j], al[i], bhj);
            }
    }
}

template <bool BTRANS, bool ASPLIT, bool BSPLIT, bool F16, typename T>
__device__ __forceinline__ void gemm_run(uint32_t sb, float acc[2][8][4],
    const T* Ahi, const T* Alo, int lda,
    const T* Bhi, const T* Blo, int ldb, int nk)
{
    constexpr int BTILE = BTRANS ? 17408 : 16384;
    constexpr uint32_t OFF_BH = ASPLIT ? 32768u : 16384u;
    constexpr uint32_t OFF_BL = OFF_BH + BTILE;
    constexpr uint32_t STAGE = OFF_BH + (BSPLIT ? 2 * BTILE : BTILE);
    const int tid = threadIdx.x;
#pragma unroll
    for (int i = 0; i < 2; i++)
#pragma unroll
        for (int j = 0; j < 8; j++)
#pragma unroll
            for (int r = 0; r < 4; r++) acc[i][j][r] = 0.0f;

#define LOAD_CHUNK(stg, c) do {                                                       \
        uint32_t base_ = sb + (stg) * STAGE;                                          \
        ld_tile_nmajor(base_, Ahi + (size_t)(c) * 64, lda, tid);                      \
        if (ASPLIT) ld_tile_nmajor(base_ + 16384, Alo + (size_t)(c) * 64, lda, tid);  \
        if (BTRANS) {                                                                 \
            ld_tile_kmajor(base_ + OFF_BH, Bhi + (size_t)(c) * 64 * ldb, ldb, tid);   \
            if (BSPLIT) ld_tile_kmajor(base_ + OFF_BL, Blo + (size_t)(c) * 64 * ldb, ldb, tid); \
        } else {                                                                      \
            ld_tile_nmajor(base_ + OFF_BH, Bhi + (size_t)(c) * 64, ldb, tid);         \
            if (BSPLIT) ld_tile_nmajor(base_ + OFF_BL, Blo + (size_t)(c) * 64, ldb, tid); \
        }                                                                             \
    } while (0)

    LOAD_CHUNK(0, 0);
    asm volatile("cp.async.commit_group;");
    for (int i = 0; i < nk; i++) {
        int st = i & 1;
        if (i + 1 < nk) {
            LOAD_CHUNK(st ^ 1, i + 1);
            asm volatile("cp.async.commit_group;");
            asm volatile("cp.async.wait_group 1;");
        } else {
            asm volatile("cp.async.wait_group 0;");
        }
        __syncthreads();
        compute_stage<BTRANS, ASPLIT, BSPLIT, F16>(sb + st * STAGE, acc, tid);
        __syncthreads();
    }
#undef LOAD_CHUNK
}

// smem sizes per config
#define SMEM_PROJ (2 * (32768 + 2 * 17408))   // 135168
#define SMEM_SIM  (2 * (16384 + 16384))       // 65536
#define SMEM_OUT  (2 * (16384 + 2 * 17408))   // 102400

// ---------------------------------------------------------------------------
// prep kernels
// ---------------------------------------------------------------------------
__global__ void bias_kernel(const float* __restrict__ table) {
    int d = blockIdx.x * blockDim.x + threadIdx.x;
    if (d >= SS) return;
    int bkt;
    if (d < 16) {
        bkt = d;
    } else {
        float t = logf((float)d * 0.0625f) * (16.0f / 2.0794415416798357f);
        int v = 16 + (int)t;
        bkt = v < 31 ? v : 31;
    }
    g_bias[d] = table[bkt] * 11.313708498984761f;
}
__global__ void split_f_kernel(const float* __restrict__ src, __nv_bfloat16* hi,
                               __nv_bfloat16* lo, size_t n) {
    size_t i = (size_t)blockIdx.x * blockDim.x + threadIdx.x;
    if (i >= n) return;
    float f = src[i];
    __nv_bfloat16 h = __float2bfloat16_rn(f);
    hi[i] = h;
    lo[i] = __float2bfloat16_rn(f - __bfloat162float(h));
}

// ---------------------------------------------------------------------------
// GEMM kernels
// ---------------------------------------------------------------------------
__global__ __launch_bounds__(256, 1) void tc_proj_qk(
    const float* __restrict__ bqk, const float* __restrict__ gamma,
    const float* __restrict__ beta)
{
    extern __shared__ __align__(1024) char smem[];
    uint32_t sb = smem_to_u32(smem);
    const int mt = blockIdx.x;
    float acc[2][8][4];
    gemm_run<true, true, true, false>(sb, acc,
                   g_xhi + (size_t)mt * 128 * DIMX, g_xlo + (size_t)mt * 128 * DIMX, DIMX,
                   g_wqk_hi, g_wqk_lo, DQK, DIMX / 64);
    const int tid = threadIdx.x, lane = tid & 31, wid = tid >> 5;
    const int wm = wid & 3, wn = wid >> 2, t4 = lane >> 2, tm4 = lane & 3;
#pragma unroll
    for (int i = 0; i < 2; i++)
#pragma unroll
        for (int rr = 0; rr < 2; rr++) {
            int row = mt * 128 + wm * 32 + i * 16 + t4 + 8 * rr;
#pragma unroll
            for (int j = 0; j < 8; j++) {
                int c = wn * 64 + j * 8 + 2 * tm4;
                float f0 = silu_f(acc[i][j][2 * rr + 0] + bqk[c]);
                float f1 = silu_f(acc[i][j][2 * rr + 1] + bqk[c + 1]);
                float q0 = f0 * gamma[c] + beta[c];
                float q1 = f1 * gamma[c + 1] + beta[c + 1];
                float k0 = f0 * gamma[DQK + c] + beta[DQK + c];
                float k1 = f1 * gamma[DQK + c + 1] + beta[DQK + c + 1];
                size_t o = (size_t)row * DQK + c;
                *reinterpret_cast<uint32_t*>(g_q + o) = pack_h2(q0, q1);
                *reinterpret_cast<uint32_t*>(g_k + o) = pack_h2(k0, k1);
            }
        }
}

__global__ __launch_bounds__(256, 1) void tc_proj_v(const float* __restrict__ bv)
{
    extern __shared__ __align__(1024) char smem[];
    uint32_t sb = smem_to_u32(smem);
    const int nt = blockIdx.x, mt = blockIdx.y;
    float acc[2][8][4];
    gemm_run<true, true, true, false>(sb, acc,
                   g_xhi + (size_t)mt * 128 * DIMX, g_xlo + (size_t)mt * 128 * DIMX, DIMX,
                   g_wv_hi + nt * 128, g_wv_lo + nt * 128, DV, DIMX / 64);
    const int tid = threadIdx.x, lane = tid & 31, wid = tid >> 5;
    const int wm = wid & 3, wn = wid >> 2, t4 = lane >> 2, tm4 = lane & 3;
#pragma unroll
    for (int i = 0; i < 2; i++)
#pragma unroll
        for (int rr = 0; rr < 2; rr++) {
            int row = mt * 128 + wm * 32 + i * 16 + t4 + 8 * rr;
#pragma unroll
            for (int j = 0; j < 8; j++) {
                int c = nt * 128 + wn * 64 + j * 8 + 2 * tm4;
                float f0 = silu_f(acc[i][j][2 * rr + 0] + bv[c]);
                float f1 = silu_f(acc[i][j][2 * rr + 1] + bv[c + 1]);
                uint32_t vh, vl;
                split2h(f0, f1, vh, vl);
                size_t o = (size_t)row * DV + c;
                *reinterpret_cast<uint32_t*>(g_vhi + o) = vh;
                *reinterpret_cast<uint32_t*>(g_vlo + o) = vl;
            }
        }
}

__global__ __launch_bounds__(256, 1) void tc_sim()
{
    extern __shared__ __align__(1024) char smem[];
    uint32_t sb = smem_to_u32(smem);
    int t = blockIdx.x;
    const int b = blockIdx.y;
    int it = 0;
    while ((it + 1) * (it + 2) / 2 <= t) it++;
    const int jt = t - it * (it + 1) / 2;
    const size_t qoff = ((size_t)b * SS + it * 128) * DQK;
    const size_t koff = ((size_t)b * SS + jt * 128) * DQK;
    float acc[2][8][4];
    gemm_run<false, false, false, true>(sb, acc, g_q + qoff, (const __half*)nullptr, DQK,
                    g_k + koff, (const __half*)nullptr, DQK, DQK / 64);
    const int tid = threadIdx.x, lane = tid & 31, wid = tid >> 5;
    const int wm = wid & 3, wn = wid >> 2, t4 = lane >> 2, tm4 = lane & 3;
    const float invS = 1.0f / (float)SS;
    const size_t bb = (size_t)b * SS * SS;
#pragma unroll
    for (int i = 0; i < 2; i++)
#pragma unroll
        for (int rr = 0; rr < 2; rr++) {
            int gi = it * 128 + wm * 32 + i * 16 + t4 + 8 * rr;
#pragma unroll
            for (int j = 0; j < 8; j++) {
                int gj = jt * 128 + wn * 64 + j * 8 + 2 * tm4;
                float v0 = 0.0f, v1 = 0.0f;
                if (gj <= gi)
                    v0 = lapl_f(acc[i][j][2 * rr + 0] * invS + g_bias[gi - gj]);
                if (gj + 1 <= gi)
                    v1 = lapl_f(acc[i][j][2 * rr + 1] * invS + g_bias[gi - gj - 1]);
                size_t o = bb + (size_t)gi * SS + gj;
                *reinterpret_cast<uint32_t*>(g_attn + o) = pack_h2(v0, v1);
            }
        }
}

__global__ __launch_bounds__(256, 1) void tc_out(float* __restrict__ out)
{
    extern __shared__ __align__(1024) char smem[];
    uint32_t sb = smem_to_u32(smem);
    const int nt = blockIdx.x;
    const int it = 15 - blockIdx.y;   // heaviest first
    const int b = blockIdx.z;
    const int nk = (it + 1) * 2;
    const size_t aoff = ((size_t)b * SS + it * 128) * SS;
    float acc[2][8][4];
    gemm_run<true, false, true, true>(sb, acc, g_attn + aoff, (const __half*)nullptr, SS,
                   g_vhi + (size_t)b * SS * DV + nt * 128,
                   g_vlo + (size_t)b * SS * DV + nt * 128, DV, nk);
    const int tid = threadIdx.x, lane = tid & 31, wid = tid >> 5;
    const int wm = wid & 3, wn = wid >> 2, t4 = lane >> 2, tm4 = lane & 3;
#pragma unroll
    for (int i = 0; i < 2; i++)
#pragma unroll
        for (int rr = 0; rr < 2; rr++) {
            int row = it * 128 + wm * 32 + i * 16 + t4 + 8 * rr;
#pragma unroll
            for (int j = 0; j < 8; j++) {
                int c = nt * 128 + wn * 64 + j * 8 + 2 * tm4;
                float2 v;
                v.x = acc[i][j][2 * rr + 0];
                v.y = acc[i][j][2 * rr + 1];
                *reinterpret_cast<float2*>(out + ((size_t)b * SS + row) * DV + c) = v;
            }
        }
}

// ---------------------------------------------------------------------------
// launch
// ---------------------------------------------------------------------------
extern "C" void kernel_launch(void* const* d_in, const int* in_sizes, int n_in,
                              void* d_out, int out_size)
{
    const float* x     = (const float*)d_in[0];
    const float* wqk   = (const float*)d_in[1];
    const float* bqk   = (const float*)d_in[2];
    const float* gamma = (const float*)d_in[3];
    const float* beta  = (const float*)d_in[4];
    const float* wv    = (const float*)d_in[5];
    const float* bv    = (const float*)d_in[6];
    const float* rel   = (const float*)d_in[7];
    float* out = (float*)d_out;

    cudaFuncSetAttribute(tc_proj_qk, cudaFuncAttributeMaxDynamicSharedMemorySize, SMEM_PROJ);
    cudaFuncSetAttribute(tc_proj_v,  cudaFuncAttributeMaxDynamicSharedMemorySize, SMEM_PROJ);
    cudaFuncSetAttribute(tc_sim,     cudaFuncAttributeMaxDynamicSharedMemorySize, SMEM_SIM);
    cudaFuncSetAttribute(tc_out,     cudaFuncAttributeMaxDynamicSharedMemorySize, SMEM_OUT);

    bias_kernel<<<(SS + 255) / 256, 256>>>(rel);
    {
        __nv_bfloat16 *xh, *xl, *wqh, *wql, *wvh, *wvl;
        cudaGetSymbolAddress((void**)&xh, g_xhi);
        cudaGetSymbolAddress((void**)&xl, g_xlo);
        cudaGetSymbolAddress((void**)&wqh, g_wqk_hi);
        cudaGetSymbolAddress((void**)&wql, g_wqk_lo);
        cudaGetSymbolAddress((void**)&wvh, g_wv_hi);
        cudaGetSymbolAddress((void**)&wvl, g_wv_lo);
        size_t nx = (size_t)MROWS * DIMX;
        split_f_kernel<<<(unsigned)((nx + 255) / 256), 256>>>(x, xh, xl, nx);
        split_f_kernel<<<(DIMX * DQK + 255) / 256, 256>>>(wqk, wqh, wql, DIMX * DQK);
        size_t nw = (size_t)DIMX * DV;
        split_f_kernel<<<(unsigned)((nw + 255) / 256), 256>>>(wv, wvh, wvl, nw);
    }

    tc_proj_qk<<<MROWS / 128, 256, SMEM_PROJ>>>(bqk, gamma, beta);
    tc_proj_v<<<dim3(DV / 128, MROWS / 128), 256, SMEM_PROJ>>>(bv);
    tc_sim<<<dim3(136, BB), 256, SMEM_SIM>>>();
    tc_out<<<dim3(DV / 128, SS / 128, BB), 256, SMEM_OUT>>>(out);
}

// round 6
// speedup vs baseline: 4.4721x; 1.6974x over previous
#include <cuda_runtime.h>
#include <cuda_fp16.h>
#include <math.h>
#include <stdint.h>

#define BB 4
#define SS 2048
#define DIMX 1024
#define DQK 128
#define DV 1024
#define MROWS (BB * SS)   // 8192

// ---------------------------------------------------------------------------
// scratch (__device__ globals; no dynamic allocation)
// ---------------------------------------------------------------------------
__device__ __align__(256) __half g_x[(size_t)MROWS * DIMX];        // fp16
__device__ __align__(256) __half g_wqk[DIMX * DQK];                // [k][n]
__device__ __align__(256) __half g_wv[(size_t)DIMX * DV];          // [k][n]
__device__ __align__(256) __half g_q[(size_t)MROWS * DQK];
__device__ __align__(256) __half g_k[(size_t)MROWS * DQK];
__device__ __align__(256) __half g_v[(size_t)MROWS * DV];          // [row][dv]
__device__ __align__(256) __half g_attn[(size_t)BB * SS * SS];
__device__ float g_bias[SS];

// ---------------------------------------------------------------------------
// helpers
// ---------------------------------------------------------------------------
__device__ __forceinline__ uint32_t smem_to_u32(const void* p) {
    uint32_t a;
    asm("{ .reg .u64 t; cvta.to.shared.u64 t, %1; cvt.u32.u64 %0, t; }"
        : "=r"(a) : "l"(p));
    return a;
}
__device__ __forceinline__ uint32_t sw128(uint32_t o) {
    return o ^ ((o >> 3) & 0x70);
}
__device__ __forceinline__ void cp16(uint32_t dst, const void* src) {
    asm volatile("cp.async.cg.shared.global [%0], [%1], 16;" :: "r"(dst), "l"(src));
}
__device__ __forceinline__ void ldmx4(uint32_t* r, uint32_t a) {
    asm volatile("ldmatrix.sync.aligned.m8n8.x4.shared.b16 {%0,%1,%2,%3}, [%4];"
        : "=r"(r[0]), "=r"(r[1]), "=r"(r[2]), "=r"(r[3]) : "r"(a));
}
__device__ __forceinline__ void ldmx4t(uint32_t* r, uint32_t a) {
    asm volatile("ldmatrix.sync.aligned.m8n8.x4.trans.shared.b16 {%0,%1,%2,%3}, [%4];"
        : "=r"(r[0]), "=r"(r[1]), "=r"(r[2]), "=r"(r[3]) : "r"(a));
}
__device__ __forceinline__ void mma16816(float* d, const uint32_t* a, const uint32_t* b) {
    asm volatile(
        "mma.sync.aligned.m16n8k16.row.col.f32.f16.f16.f32 "
        "{%0,%1,%2,%3}, {%4,%5,%6,%7}, {%8,%9}, {%0,%1,%2,%3};"
        : "+f"(d[0]), "+f"(d[1]), "+f"(d[2]), "+f"(d[3])
        : "r"(a[0]), "r"(a[1]), "r"(a[2]), "r"(a[3]), "r"(b[0]), "r"(b[1]));
}

__device__ __forceinline__ float silu_f(float x) { return x / (1.0f + expf(-x)); }
__device__ __forceinline__ float lapl_f(float x) {
    return 0.5f * (1.0f + erff((x - 0.70710678118654746f) * 0.79788456080286541f));
}
__device__ __forceinline__ uint32_t pack_h2(float a, float b) {
    __half2 h2 = __floats2half2_rn(a, b);
    return *reinterpret_cast<uint32_t*>(&h2);
}

// ---------------------------------------------------------------------------
// tile geometry: CTA 128x128, chunk K=64, 256 threads, 8 warps (4m x 2n),
// warp tile 32x64. A/B(nmajor) tiles: 128 rows x 128B, SW128 swizzle.
// B(kmajor/trans) tiles: 64 rows x 272B (256B data + 16B pad).
// ---------------------------------------------------------------------------
__device__ __forceinline__ void ld_tile_nmajor(uint32_t dst, const __half* src,
                                               int ld, int tid) {
#pragma unroll
    for (int s = 0; s < 4; s++) {
        int idx = tid + s * 256;
        int row = idx >> 3, seg = idx & 7;
        uint32_t off = (uint32_t)(row * 128 + seg * 16);
        cp16(dst + sw128(off), src + (size_t)row * ld + seg * 8);
    }
}
__device__ __forceinline__ void ld_tile_kmajor(uint32_t dst, const __half* src,
                                               int ld, int tid) {
#pragma unroll
    for (int s = 0; s < 4; s++) {
        int idx = tid + s * 256;
        int row = idx >> 4, seg = idx & 15;
        cp16(dst + (uint32_t)(row * 272 + seg * 16), src + (size_t)row * ld + seg * 8);
    }
}

template <bool BTRANS>
__device__ __forceinline__ void compute_stage(uint32_t st, float acc[2][8][4], int tid) {
    const int lane = tid & 31, wid = tid >> 5, wm = wid & 3, wn = wid >> 2;
    uint32_t a_raw[2];
#pragma unroll
    for (int i = 0; i < 2; i++) {
        uint32_t row = wm * 32 + i * 16 + (lane & 15);
        a_raw[i] = row * 128 + ((lane >> 4) << 4);
    }
    uint32_t b_raw[4];
    const uint32_t m = lane >> 3;
    if (!BTRANS) {
#pragma unroll
        for (int g = 0; g < 4; g++) {
            uint32_t row = wn * 64 + g * 16 + ((m >> 1) << 3) + (lane & 7);
            b_raw[g] = row * 128 + ((m & 1) << 4);
        }
    } else {
#pragma unroll
        for (int g = 0; g < 4; g++) {
            uint32_t krow = ((m & 1) << 3) + (lane & 7);
            uint32_t ncol = wn * 64 + g * 16 + ((m >> 1) << 3);
            b_raw[g] = krow * 272 + ncol * 2;
        }
    }
    const uint32_t A_s = st, B_s = st + 16384;
#pragma unroll
    for (int ks = 0; ks < 4; ks++) {
        uint32_t ah[2][4], bh[4][4];
#pragma unroll
        for (int i = 0; i < 2; i++)
            ldmx4(ah[i], A_s + sw128(a_raw[i] + ks * 32));
        if (!BTRANS) {
#pragma unroll
            for (int g = 0; g < 4; g++)
                ldmx4(bh[g], B_s + sw128(b_raw[g] + ks * 32));
        } else {
#pragma unroll
            for (int g = 0; g < 4; g++)
                ldmx4t(bh[g], B_s + b_raw[g] + ks * 4352);
        }
#pragma unroll
        for (int i = 0; i < 2; i++)
#pragma unroll
            for (int j = 0; j < 8; j++)
                mma16816(acc[i][j], ah[i], &bh[j >> 1][(j & 1) * 2]);
    }
}

template <bool BTRANS>
__device__ __forceinline__ void gemm_run(uint32_t sb, float acc[2][8][4],
    const __half* A, int lda, const __half* B, int ldb, int nk)
{
    constexpr uint32_t BTILE = BTRANS ? 17408u : 16384u;
    constexpr uint32_t STAGE = 16384u + BTILE;
    const int tid = threadIdx.x;
#pragma unroll
    for (int i = 0; i < 2; i++)
#pragma unroll
        for (int j = 0; j < 8; j++)
#pragma unroll
            for (int r = 0; r < 4; r++) acc[i][j][r] = 0.0f;

#define LOAD_CHUNK(stg, c) do {                                                      \
        uint32_t base_ = sb + (stg) * STAGE;                                         \
        ld_tile_nmajor(base_, A + (size_t)(c) * 64, lda, tid);                       \
        if (BTRANS) ld_tile_kmajor(base_ + 16384, B + (size_t)(c) * 64 * ldb, ldb, tid); \
        else        ld_tile_nmajor(base_ + 16384, B + (size_t)(c) * 64, ldb, tid);   \
    } while (0)

    LOAD_CHUNK(0, 0);
    asm volatile("cp.async.commit_group;");
    for (int i = 0; i < nk; i++) {
        int st = i & 1;
        if (i + 1 < nk) {
            LOAD_CHUNK(st ^ 1, i + 1);
            asm volatile("cp.async.commit_group;");
            asm volatile("cp.async.wait_group 1;");
        } else {
            asm volatile("cp.async.wait_group 0;");
        }
        __syncthreads();
        compute_stage<BTRANS>(sb + st * STAGE, acc, tid);
        __syncthreads();
    }
#undef LOAD_CHUNK
}

#define SMEM_PROJ (2 * (16384 + 17408))   // 67584 (BTRANS)
#define SMEM_SIM  (2 * (16384 + 16384))   // 65536
#define SMEM_OUT  (2 * (16384 + 17408))   // 67584

// ---------------------------------------------------------------------------
// prep kernels
// ---------------------------------------------------------------------------
__global__ void bias_kernel(const float* __restrict__ table) {
    int d = blockIdx.x * blockDim.x + threadIdx.x;
    if (d >= SS) return;
    int bkt;
    if (d < 16) {
        bkt = d;
    } else {
        float t = logf((float)d * 0.0625f) * (16.0f / 2.0794415416798357f);
        int v = 16 + (int)t;
        bkt = v < 31 ? v : 31;
    }
    g_bias[d] = table[bkt] * 11.313708498984761f;
}
__global__ void cvt_f_kernel(const float* __restrict__ src, __half* dst, size_t n) {
    size_t i = ((size_t)blockIdx.x * blockDim.x + threadIdx.x) * 4;
    if (i >= n) return;
    float4 f = *reinterpret_cast<const float4*>(src + i);
    uint2 o;
    o.x = pack_h2(f.x, f.y);
    o.y = pack_h2(f.z, f.w);
    *reinterpret_cast<uint2*>(dst + i) = o;
}

// ---------------------------------------------------------------------------
// GEMM kernels
// ---------------------------------------------------------------------------
__global__ __launch_bounds__(256, 1) void tc_proj_qk(
    const float* __restrict__ bqk, const float* __restrict__ gamma,
    const float* __restrict__ beta)
{
    extern __shared__ __align__(1024) char smem[];
    uint32_t sb = smem_to_u32(smem);
    const int mt = blockIdx.x;
    float acc[2][8][4];
    gemm_run<true>(sb, acc, g_x + (size_t)mt * 128 * DIMX, DIMX,
                   g_wqk, DQK, DIMX / 64);
    const int tid = threadIdx.x, lane = tid & 31, wid = tid >> 5;
    const int wm = wid & 3, wn = wid >> 2, t4 = lane >> 2, tm4 = lane & 3;
#pragma unroll
    for (int i = 0; i < 2; i++)
#pragma unroll
        for (int rr = 0; rr < 2; rr++) {
            int row = mt * 128 + wm * 32 + i * 16 + t4 + 8 * rr;
#pragma unroll
            for (int j = 0; j < 8; j++) {
                int c = wn * 64 + j * 8 + 2 * tm4;
                float f0 = silu_f(acc[i][j][2 * rr + 0] + bqk[c]);
                float f1 = silu_f(acc[i][j][2 * rr + 1] + bqk[c + 1]);
                float q0 = f0 * gamma[c] + beta[c];
                float q1 = f1 * gamma[c + 1] + beta[c + 1];
                float k0 = f0 * gamma[DQK + c] + beta[DQK + c];
                float k1 = f1 * gamma[DQK + c + 1] + beta[DQK + c + 1];
                size_t o = (size_t)row * DQK + c;
                *reinterpret_cast<uint32_t*>(g_q + o) = pack_h2(q0, q1);
                *reinterpret_cast<uint32_t*>(g_k + o) = pack_h2(k0, k1);
            }
        }
}

__global__ __launch_bounds__(256, 1) void tc_proj_v(const float* __restrict__ bv)
{
    extern __shared__ __align__(1024) char smem[];
    uint32_t sb = smem_to_u32(smem);
    const int nt = blockIdx.x, mt = blockIdx.y;
    float acc[2][8][4];
    gemm_run<true>(sb, acc, g_x + (size_t)mt * 128 * DIMX, DIMX,
                   g_wv + nt * 128, DV, DIMX / 64);
    const int tid = threadIdx.x, lane = tid & 31, wid = tid >> 5;
    const int wm = wid & 3, wn = wid >> 2, t4 = lane >> 2, tm4 = lane & 3;
#pragma unroll
    for (int i = 0; i < 2; i++)
#pragma unroll
        for (int rr = 0; rr < 2; rr++) {
            int row = mt * 128 + wm * 32 + i * 16 + t4 + 8 * rr;
#pragma unroll
            for (int j = 0; j < 8; j++) {
                int c = nt * 128 + wn * 64 + j * 8 + 2 * tm4;
                float f0 = silu_f(acc[i][j][2 * rr + 0] + bv[c]);
                float f1 = silu_f(acc[i][j][2 * rr + 1] + bv[c + 1]);
                *reinterpret_cast<uint32_t*>(g_v + (size_t)row * DV + c) = pack_h2(f0, f1);
            }
        }
}

__global__ __launch_bounds__(256, 1) void tc_sim()
{
    extern __shared__ __align__(1024) char smem[];
    uint32_t sb = smem_to_u32(smem);
    int t = blockIdx.x;
    const int b = blockIdx.y;
    int it = 0;
    while ((it + 1) * (it + 2) / 2 <= t) it++;
    const int jt = t - it * (it + 1) / 2;
    const size_t qoff = ((size_t)b * SS + it * 128) * DQK;
    const size_t koff = ((size_t)b * SS + jt * 128) * DQK;
    float acc[2][8][4];
    gemm_run<false>(sb, acc, g_q + qoff, DQK, g_k + koff, DQK, DQK / 64);
    const int tid = threadIdx.x, lane = tid & 31, wid = tid >> 5;
    const int wm = wid & 3, wn = wid >> 2, t4 = lane >> 2, tm4 = lane & 3;
    const float invS = 1.0f / (float)SS;
    const size_t bb = (size_t)b * SS * SS;
#pragma unroll
    for (int i = 0; i < 2; i++)
#pragma unroll
        for (int rr = 0; rr < 2; rr++) {
            int gi = it * 128 + wm * 32 + i * 16 + t4 + 8 * rr;
#pragma unroll
            for (int j = 0; j < 8; j++) {
                int gj = jt * 128 + wn * 64 + j * 8 + 2 * tm4;
                float v0 = 0.0f, v1 = 0.0f;
                if (gj <= gi)
                    v0 = lapl_f(acc[i][j][2 * rr + 0] * invS + g_bias[gi - gj]);
                if (gj + 1 <= gi)
                    v1 = lapl_f(acc[i][j][2 * rr + 1] * invS + g_bias[gi - gj - 1]);
                size_t o = bb + (size_t)gi * SS + gj;
                *reinterpret_cast<uint32_t*>(g_attn + o) = pack_h2(v0, v1);
            }
        }
}

__global__ __launch_bounds__(256, 1) void tc_out(float* __restrict__ out)
{
    extern __shared__ __align__(1024) char smem[];
    uint32_t sb = smem_to_u32(smem);
    const int nt = blockIdx.x;
    const int it = 15 - blockIdx.y;   // heaviest first
    const int b = blockIdx.z;
    const int nk = (it + 1) * 2;
    const size_t aoff = ((size_t)b * SS + it * 128) * SS;
    float acc[2][8][4];
    gemm_run<true>(sb, acc, g_attn + aoff, SS,
                   g_v + (size_t)b * SS * DV + nt * 128, DV, nk);
    const int tid = threadIdx.x, lane = tid & 31, wid = tid >> 5;
    const int wm = wid & 3, wn = wid >> 2, t4 = lane >> 2, tm4 = lane & 3;
#pragma unroll
    for (int i = 0; i < 2; i++)
#pragma unroll
        for (int rr = 0; rr < 2; rr++) {
            int row = it * 128 + wm * 32 + i * 16 + t4 + 8 * rr;
#pragma unroll
            for (int j = 0; j < 8; j++) {
                int c = nt * 128 + wn * 64 + j * 8 + 2 * tm4;
                float2 v;
                v.x = acc[i][j][2 * rr + 0];
                v.y = acc[i][j][2 * rr + 1];
                *reinterpret_cast<float2*>(out + ((size_t)b * SS + row) * DV + c) = v;
            }
        }
}

// ---------------------------------------------------------------------------
// launch
// ---------------------------------------------------------------------------
extern "C" void kernel_launch(void* const* d_in, const int* in_sizes, int n_in,
                              void* d_out, int out_size)
{
    const float* x     = (const float*)d_in[0];
    const float* wqk   = (const float*)d_in[1];
    const float* bqk   = (const float*)d_in[2];
    const float* gamma = (const float*)d_in[3];
    const float* beta  = (const float*)d_in[4];
    const float* wv    = (const float*)d_in[5];
    const float* bv    = (const float*)d_in[6];
    const float* rel   = (const float*)d_in[7];
    float* out = (float*)d_out;

    cudaFuncSetAttribute(tc_proj_qk, cudaFuncAttributeMaxDynamicSharedMemorySize, SMEM_PROJ);
    cudaFuncSetAttribute(tc_proj_v,  cudaFuncAttributeMaxDynamicSharedMemorySize, SMEM_PROJ);
    cudaFuncSetAttribute(tc_sim,     cudaFuncAttributeMaxDynamicSharedMemorySize, SMEM_SIM);
    cudaFuncSetAttribute(tc_out,     cudaFuncAttributeMaxDynamicSharedMemorySize, SMEM_OUT);

    bias_kernel<<<(SS + 255) / 256, 256>>>(rel);
    {
        __half *xh, *wqh, *wvh;
        cudaGetSymbolAddress((void**)&xh, g_x);
        cudaGetSymbolAddress((void**)&wqh, g_wqk);
        cudaGetSymbolAddress((void**)&wvh, g_wv);
        size_t nx = (size_t)MROWS * DIMX;
        cvt_f_kernel<<<(unsigned)((nx / 4 + 255) / 256), 256>>>(x, xh, nx);
        cvt_f_kernel<<<(DIMX * DQK / 4 + 255) / 256, 256>>>(wqk, wqh, DIMX * DQK);
        size_t nw = (size_t)DIMX * DV;
        cvt_f_kernel<<<(unsigned)((nw / 4 + 255) / 256), 256>>>(wv, wvh, nw);
    }

    tc_proj_qk<<<MROWS / 128, 256, SMEM_PROJ>>>(bqk, gamma, beta);
    tc_proj_v<<<dim3(DV / 128, MROWS / 128), 256, SMEM_PROJ>>>(bv);
    tc_sim<<<dim3(136, BB), 256, SMEM_SIM>>>();
    tc_out<<<dim3(DV / 128, SS / 128, BB), 256, SMEM_OUT>>>(out);
}